// round 15
// baseline (speedup 1.0000x reference)
#include <cuda_runtime.h>
#include <cuda_fp16.h>
#include <math.h>
#include <stdint.h>

#define T_TOK   4096
#define D_DIM   1024
#define H_DIM   512
#define HS_DIM  1024
#define E_NUM   32
#define TOPK    4
#define P_PAIRS (T_TOK*TOPK)
#define CAP     2048

#define BM 128
#define BK 64
#define STAGE_BYTES 32768
#define N_STAGE 3
#define DYN_SMEM (N_STAGE*STAGE_BYTES)   // 98304

// ---------------- scratch ----------------
__device__ int   g_pair_e[P_PAIRS];
__device__ float g_pair_w[P_PAIRS];
__device__ int   g_pair_pos[P_PAIRS];
__device__ int   g_slot_tok[E_NUM*CAP];
__device__ float g_slot_w[E_NUM*CAP];
__device__ int   g_count[E_NUM];
__device__ __align__(16) __half g_pairbuf[(size_t)E_NUM*CAP*D_DIM];
__device__ __align__(16) __half g_hexp[(size_t)E_NUM*CAP*H_DIM];
__device__ __align__(16) __half g_hsh[(size_t)T_TOK*HS_DIM];
__device__ __align__(16) __half g_X[(size_t)T_TOK*D_DIM];
__device__ __align__(16) __half g_W1[(size_t)E_NUM*D_DIM*H_DIM];
__device__ __align__(16) __half g_W3[(size_t)E_NUM*D_DIM*H_DIM];
__device__ __align__(16) __half g_W2[(size_t)E_NUM*H_DIM*D_DIM];
__device__ __align__(16) __half g_Ws1[(size_t)D_DIM*HS_DIM];
__device__ __align__(16) __half g_Ws3[(size_t)D_DIM*HS_DIM];
__device__ __align__(16) __half g_Ws2[(size_t)HS_DIM*D_DIM];

// ---------------- helpers ----------------
__device__ __forceinline__ uint32_t smem_u32(const void* p) {
    return (uint32_t)__cvta_generic_to_shared(p);
}
__device__ __forceinline__ void cpa16(uint32_t dst, const void* src) {
    asm volatile("cp.async.cg.shared.global [%0], [%1], 16;" :: "r"(dst), "l"(src));
}
__device__ __forceinline__ void cpa16z(uint32_t dst, const void* src, bool valid) {
    int sz = valid ? 16 : 0;
    asm volatile("cp.async.cg.shared.global [%0], [%1], 16, %2;" :: "r"(dst), "l"(src), "r"(sz));
}
__device__ __forceinline__ void cpa_commit() { asm volatile("cp.async.commit_group;"); }
__device__ __forceinline__ void cpa_wait0()  { asm volatile("cp.async.wait_group 0;"); }
__device__ __forceinline__ void cpa_wait1()  { asm volatile("cp.async.wait_group 1;"); }
__device__ __forceinline__ void ldsm_x4(uint32_t* r, uint32_t a) {
    asm volatile("ldmatrix.sync.aligned.m8n8.x4.shared.b16 {%0,%1,%2,%3}, [%4];"
        : "=r"(r[0]), "=r"(r[1]), "=r"(r[2]), "=r"(r[3]) : "r"(a));
}
__device__ __forceinline__ void ldsm_x4_t(uint32_t* r, uint32_t a) {
    asm volatile("ldmatrix.sync.aligned.m8n8.x4.trans.shared.b16 {%0,%1,%2,%3}, [%4];"
        : "=r"(r[0]), "=r"(r[1]), "=r"(r[2]), "=r"(r[3]) : "r"(a));
}
__device__ __forceinline__ void mma16816(float* c, const uint32_t* a, const uint32_t* b) {
    asm volatile(
        "mma.sync.aligned.m16n8k16.row.col.f32.f16.f16.f32 "
        "{%0,%1,%2,%3}, {%4,%5,%6,%7}, {%8,%9}, {%0,%1,%2,%3};"
        : "+f"(c[0]), "+f"(c[1]), "+f"(c[2]), "+f"(c[3])
        : "r"(a[0]), "r"(a[1]), "r"(a[2]), "r"(a[3]), "r"(b[0]), "r"(b[1]));
}
__device__ __forceinline__ uint2 conv4h(float4 v) {
    __half2 ab = __floats2half2_rn(v.x, v.y);
    __half2 cd = __floats2half2_rn(v.z, v.w);
    return make_uint2(*(uint32_t*)&ab, *(uint32_t*)&cd);
}
// swizzled offset: RB-byte rows, s = 16B chunk index, XOR by row&7
__device__ __forceinline__ uint32_t b_off(int r, int s, int RB) {
    return (uint32_t)r*(uint32_t)RB + (uint32_t)((s ^ (r&7)) << 4);
}

// ---------------- converts ----------------
__global__ __launch_bounds__(256)
void conv2_kernel(const float4* __restrict__ sA, uint2* __restrict__ oA,
                  const float4* __restrict__ sB, uint2* __restrict__ oB, int n4)
{
    for (int i = blockIdx.x*blockDim.x + threadIdx.x; i < n4; i += gridDim.x*blockDim.x) {
        oA[i] = conv4h(sA[i]);
        oB[i] = conv4h(sB[i]);
    }
}
#define N4_W2  ((int)((size_t)E_NUM*H_DIM*D_DIM/4))
#define N4_WS  ((int)((size_t)D_DIM*HS_DIM/4))
__global__ __launch_bounds__(256)
void convtail_kernel(const float4* __restrict__ W2, uint2* __restrict__ oW2,
                     const float4* __restrict__ Ws1, uint2* __restrict__ oWs1,
                     const float4* __restrict__ Ws3, uint2* __restrict__ oWs3,
                     const float4* __restrict__ Ws2, uint2* __restrict__ oWs2)
{
    int total = N4_W2 + 3*N4_WS;
    for (int i = blockIdx.x*blockDim.x + threadIdx.x; i < total; i += gridDim.x*blockDim.x) {
        if (i < N4_W2) {
            oW2[i] = conv4h(W2[i]);
        } else {
            int j = i - N4_W2;
            if (j < N4_WS) oWs1[j] = conv4h(Ws1[j]);
            else if (j < 2*N4_WS) oWs3[j - N4_WS] = conv4h(Ws3[j - N4_WS]);
            else oWs2[j - 2*N4_WS] = conv4h(Ws2[j - 2*N4_WS]);
        }
    }
}

// ---------------- gating: lane = expert, coalesced Wg; also emits fp16 X -------
__global__ __launch_bounds__(256)
void gate_kernel(const float* __restrict__ X, const float* __restrict__ Wg)
{
    int warp = (blockIdx.x*blockDim.x + threadIdx.x) >> 5;
    int lane = threadIdx.x & 31;
    if (warp >= T_TOK) return;
    const float* xr = X + (size_t)warp * D_DIM;
    float xv[32];
    #pragma unroll
    for (int i = 0; i < 32; i++) xv[i] = xr[lane + 32*i];

    __half* xo = g_X + (size_t)warp * D_DIM;
    #pragma unroll
    for (int i = 0; i < 32; i++) xo[lane + 32*i] = __float2half_rn(xv[i]);

    float logit = 0.f;
    #pragma unroll 4
    for (int i0 = 0; i0 < 32; i0++) {
        float xi = xv[i0];
        const float* wrow = Wg + (size_t)(32*i0)*E_NUM + lane;
        #pragma unroll
        for (int l = 0; l < 32; l++) {
            float xk = __shfl_sync(0xffffffffu, xi, l);
            logit += xk * wrow[(size_t)l*E_NUM];
        }
    }

    float m = logit;
    #pragma unroll
    for (int off = 16; off; off >>= 1) m = fmaxf(m, __shfl_xor_sync(0xffffffffu, m, off));
    float p = expf(logit - m);
    float s = p;
    #pragma unroll
    for (int off = 16; off; off >>= 1) s += __shfl_xor_sync(0xffffffffu, s, off);
    float prob = p / s;

    for (int k = 0; k < TOPK; k++) {
        float v = prob; int idx = lane;
        #pragma unroll
        for (int off = 16; off; off >>= 1) {
            float ov = __shfl_xor_sync(0xffffffffu, v, off);
            int   oi = __shfl_xor_sync(0xffffffffu, idx, off);
            if (ov > v || (ov == v && oi < idx)) { v = ov; idx = oi; }
        }
        if (lane == 0) {
            g_pair_e[warp*TOPK + k] = idx;
            g_pair_w[warp*TOPK + k] = v;
        }
        if (lane == idx) prob = -1.f;
    }
}

// ---------------- dispatch ----------------
__global__ __launch_bounds__(256)
void dispatch_kernel()
{
    int e = blockIdx.x;
    int tid = threadIdx.x;
    int lane = tid & 31, wid = tid >> 5;
    __shared__ int wtot[8];
    __shared__ int s_run;
    if (tid == 0) s_run = 0;
    __syncthreads();

    for (int base = 0; base < P_PAIRS; base += 256) {
        int p = base + tid;
        int flag = (g_pair_e[p] == e) ? 1 : 0;
        unsigned b = __ballot_sync(0xffffffffu, flag);
        int woff = __popc(b & ((1u << lane) - 1u));
        if (lane == 0) wtot[wid] = __popc(b);
        __syncthreads();
        int excl = 0, tot = 0;
        #pragma unroll
        for (int w = 0; w < 8; w++) { if (w < wid) excl += wtot[w]; tot += wtot[w]; }
        int pos = s_run + excl + woff;
        if (flag) {
            if (pos < CAP) {
                g_slot_tok[e*CAP + pos] = p >> 2;
                g_slot_w  [e*CAP + pos] = g_pair_w[p];
                g_pair_pos[p] = e*CAP + pos;
            } else {
                g_pair_pos[p] = -1;
            }
        }
        __syncthreads();
        if (tid == 0) s_run += tot;
        __syncthreads();
    }
    if (tid == 0) g_count[e] = min(s_run, CAP);
}

// =====================================================================
// up: block 128x64, 256 thr, occ 2, warps 2Mx4N, BK=64, 3-stage
// stage: A 0 (16K, RB=128) B1 16384 (8K, RB=128) B3 24576 (8K) = 32K
// =====================================================================
__global__ __launch_bounds__(256, 2)
void up_mma(int NN, int expert_mode)
{
    extern __shared__ char sm[];
    uint32_t sbase = smem_u32(sm);

    int e = blockIdx.z;
    int M_eff; const int* rows = nullptr;
    const __half *B1_g, *B3_g;
    __half *Hh;
    if (expert_mode) {
        M_eff = g_count[e];
        rows  = g_slot_tok + e*CAP;
        size_t wo = (size_t)e*D_DIM*H_DIM;
        B1_g = g_W1 + wo; B3_g = g_W3 + wo;
        Hh = g_hexp + (size_t)e*CAP*NN;
    } else {
        M_eff = T_TOK;
        B1_g = g_Ws1; B3_g = g_Ws3;
        Hh = g_hsh;
    }
    int mbase = blockIdx.x * BM;
    if (mbase >= M_eff) return;
    int nbase = blockIdx.y * 64;
    const int KK = D_DIM;
    const int NT = KK / BK;   // 16

    int tid = threadIdx.x, lane = tid & 31, wid = tid >> 5;
    int wm = wid >> 2, wn = wid & 3;

    // A staging: 128 rows x 8 chunks = 1024; thread -> row tid>>1, chunks (tid&1)*4 + j
    int arow = tid >> 1, acb = (tid & 1) * 4;
    bool avA = (mbase + arow) < M_eff;
    int tok = avA ? (rows ? rows[mbase + arow] : (mbase + arow)) : 0;
    const __half* XP = g_X + (size_t)tok*KK + acb*8;
    // B staging: 64 k-rows x 8 chunks = 512 per matrix; thread -> row tid>>2, chunks (tid&3)*2 + j
    int brow = tid >> 2, bcb = (tid & 3) * 2;

    auto load_stage = [&](int s, int kt) {
        uint32_t st = sbase + (uint32_t)s*STAGE_BYTES;
        #pragma unroll
        for (int j = 0; j < 4; j++)
            cpa16z(st + b_off(arow, acb + j, 128), XP + kt + j*8, avA);
        #pragma unroll
        for (int j = 0; j < 2; j++) {
            uint32_t d = b_off(brow, bcb + j, 128);
            size_t src = (size_t)(kt + brow)*NN + nbase + (bcb + j)*8;
            cpa16(st + 16384 + d, B1_g + src);
            cpa16(st + 24576 + d, B3_g + src);
        }
        cpa_commit();
    };

    float c1[4][2][4] = {}, c3[4][2][4] = {};

    load_stage(0, 0);
    load_stage(1, BK);
    for (int t = 0; t < NT; t++) {
        int s = t % N_STAGE;
        if (t < NT - 1) cpa_wait1(); else cpa_wait0();
        __syncthreads();
        if (t + 2 < NT) load_stage((t + 2) % N_STAGE, (t + 2) * BK);

        uint32_t st = sbase + (uint32_t)s*STAGE_BYTES;
        #pragma unroll
        for (int ks = 0; ks < 4; ks++) {
            int k0 = ks * 16;
            int rr = k0 + (lane & 7) + ((lane >> 3) & 1) * 8;
            int cc = wn*16 + (lane >> 4) * 8;
            uint32_t boff = b_off(rr, cc >> 3, 128);
            uint32_t b1[4], b3[4];
            ldsm_x4_t(b1, st + 16384 + boff);
            ldsm_x4_t(b3, st + 24576 + boff);
            #pragma unroll
            for (int mt = 0; mt < 4; mt++) {
                int r = wm*64 + mt*16 + (lane & 15);
                int sA = (k0 >> 3) + (lane >> 4);
                uint32_t ah[4];
                ldsm_x4(ah, st + b_off(r, sA, 128));
                #pragma unroll
                for (int nt = 0; nt < 2; nt++) {
                    mma16816(c1[mt][nt], ah, &b1[nt*2]);
                    mma16816(c3[mt][nt], ah, &b3[nt*2]);
                }
            }
        }
    }

    int r0 = lane >> 2, cb = (lane & 3) * 2;
    #pragma unroll
    for (int mt = 0; mt < 4; mt++)
        #pragma unroll
        for (int nt = 0; nt < 2; nt++) {
            int n = nbase + wn*16 + nt*8 + cb;
            #pragma unroll
            for (int p = 0; p < 2; p++) {
                int m = mbase + wm*64 + mt*16 + r0 + p*8;
                if (m < M_eff) {
                    float g0 = c1[mt][nt][2*p+0], g1 = c1[mt][nt][2*p+1];
                    float v0 = g0 / (1.f + expf(-g0)) * c3[mt][nt][2*p+0];
                    float v1 = g1 / (1.f + expf(-g1)) * c3[mt][nt][2*p+1];
                    __half2 hv = __floats2half2_rn(v0, v1);
                    *(uint32_t*)&Hh[(size_t)m*NN + n] = *(uint32_t*)&hv;
                }
            }
        }
}

// =====================================================================
// down: block 128x128, 256 thr, occ 2, warps 2Mx4N, BK=64, 3-stage
// stage: A 0 (16K, RB=128) B 16384 (16K, RB=256) = 32K
// expert mode: weighted rows -> fp16 pairbuf
// shared mode: dense store to out, FUSED with pairbuf combine (runs last)
// =====================================================================
__global__ __launch_bounds__(256, 2)
void down_mma(int KK, int expert_mode, float* __restrict__ out)
{
    extern __shared__ char sm[];
    uint32_t sbase = smem_u32(sm);

    int e = blockIdx.z;
    int M_eff; const float* wv = nullptr;
    const __half *A_g, *B_g;
    if (expert_mode) {
        M_eff = g_count[e];
        wv    = g_slot_w  + e*CAP;
        B_g   = g_W2 + (size_t)e*H_DIM*D_DIM;
        A_g   = g_hexp + (size_t)e*CAP*KK;
    } else {
        M_eff = T_TOK;
        B_g   = g_Ws2;
        A_g   = g_hsh;
    }
    int mbase = blockIdx.x * BM;
    if (mbase >= M_eff) return;
    int nbase = blockIdx.y * 128;
    const int NT = KK / BK;

    int tid = threadIdx.x, lane = tid & 31, wid = tid >> 5;
    int wm = wid >> 2, wn = wid & 3;

    int arow = tid >> 1, acb = (tid & 1) * 4;
    bool avA = (mbase + arow) < M_eff;
    int rr0 = avA ? (mbase + arow) : mbase;
    const __half* AP = A_g + (size_t)rr0*KK + acb*8;
    // B staging: 64 k-rows x 16 chunks = 1024; thread -> row tid>>2, chunks (tid&3)*4 + j
    int brow = tid >> 2, bcb = (tid & 3) * 4;

    auto load_stage = [&](int s, int kt) {
        uint32_t st = sbase + (uint32_t)s*STAGE_BYTES;
        #pragma unroll
        for (int j = 0; j < 4; j++)
            cpa16z(st + b_off(arow, acb + j, 128), AP + kt + j*8, avA);
        #pragma unroll
        for (int j = 0; j < 4; j++) {
            uint32_t d = b_off(brow, bcb + j, 256);
            cpa16(st + 16384 + d,
                  B_g + (size_t)(kt + brow)*D_DIM + nbase + (bcb + j)*8);
        }
        cpa_commit();
    };

    float c[4][4][4] = {};

    load_stage(0, 0);
    load_stage(1, BK);
    for (int t = 0; t < NT; t++) {
        int s = t % N_STAGE;
        if (t < NT - 1) cpa_wait1(); else cpa_wait0();
        __syncthreads();
        if (t + 2 < NT) load_stage((t + 2) % N_STAGE, (t + 2) * BK);

        uint32_t st = sbase + (uint32_t)s*STAGE_BYTES;
        #pragma unroll
        for (int ks = 0; ks < 4; ks++) {
            int k0 = ks * 16;
            int rr = k0 + (lane & 7) + ((lane >> 3) & 1) * 8;
            uint32_t bf[2][4];
            #pragma unroll
            for (int h = 0; h < 2; h++) {
                int cc = wn*32 + h*16 + (lane >> 4) * 8;
                ldsm_x4_t(bf[h], st + 16384 + b_off(rr, cc >> 3, 256));
            }
            #pragma unroll
            for (int mt = 0; mt < 4; mt++) {
                int r = wm*64 + mt*16 + (lane & 15);
                int sA = (k0 >> 3) + (lane >> 4);
                uint32_t ah[4];
                ldsm_x4(ah, st + b_off(r, sA, 128));
                #pragma unroll
                for (int nt = 0; nt < 4; nt++)
                    mma16816(c[mt][nt], ah, &bf[nt>>1][(nt&1)*2]);
            }
        }
    }

    int r0 = lane >> 2, cb = (lane & 3) * 2;
    #pragma unroll
    for (int mt = 0; mt < 4; mt++) {
        #pragma unroll
        for (int p = 0; p < 2; p++) {
            int m = mbase + wm*64 + mt*16 + r0 + p*8;
            if (m >= M_eff) continue;
            if (expert_mode) {
                float w = wv[m];
                __half* orow = g_pairbuf + (size_t)(e*CAP + m)*D_DIM;
                #pragma unroll
                for (int nt = 0; nt < 4; nt++) {
                    int n = nbase + wn*32 + nt*8 + cb;
                    __half2 hv = __floats2half2_rn(c[mt][nt][2*p+0] * w,
                                                   c[mt][nt][2*p+1] * w);
                    *(uint32_t*)&orow[n] = *(uint32_t*)&hv;
                }
            } else {
                int4 pos4 = *(const int4*)&g_pair_pos[m*TOPK];
                int posv[4] = {pos4.x, pos4.y, pos4.z, pos4.w};
                float* orow = out + (size_t)m*D_DIM;
                #pragma unroll
                for (int nt = 0; nt < 4; nt++) {
                    int n = nbase + wn*32 + nt*8 + cb;
                    float v0 = c[mt][nt][2*p+0], v1 = c[mt][nt][2*p+1];
                    #pragma unroll
                    for (int k = 0; k < TOPK; k++) {
                        if (posv[k] >= 0) {
                            uint32_t hv = *(const uint32_t*)
                                &g_pairbuf[(size_t)posv[k]*D_DIM + n];
                            float2 f = __half22float2(*(__half2*)&hv);
                            v0 += f.x; v1 += f.y;
                        }
                    }
                    *(float2*)&orow[n] = make_float2(v0, v1);
                }
            }
        }
    }
}

// ---------------- host launcher ----------------
extern "C" void kernel_launch(void* const* d_in, const int* in_sizes, int n_in,
                              void* d_out, int out_size)
{
    const float* x   = (const float*)d_in[0];
    const float* Wg  = (const float*)d_in[1];
    const float* W1  = (const float*)d_in[2];
    const float* W2  = (const float*)d_in[3];
    const float* W3  = (const float*)d_in[4];
    const float* Ws1 = (const float*)d_in[5];
    const float* Ws2 = (const float*)d_in[6];
    const float* Ws3 = (const float*)d_in[7];
    float* out = (float*)d_out;

    cudaFuncSetAttribute(up_mma,   cudaFuncAttributeMaxDynamicSharedMemorySize, DYN_SMEM);
    cudaFuncSetAttribute(down_mma, cudaFuncAttributeMaxDynamicSharedMemorySize, DYN_SMEM);

    void *w1, *w3, *w2, *ws1, *ws3, *ws2;
    cudaGetSymbolAddress(&w1, g_W1);  cudaGetSymbolAddress(&w3, g_W3);
    cudaGetSymbolAddress(&w2, g_W2);
    cudaGetSymbolAddress(&ws1, g_Ws1); cudaGetSymbolAddress(&ws3, g_Ws3);
    cudaGetSymbolAddress(&ws2, g_Ws2);

    gate_kernel<<<T_TOK/8, 256>>>(x, Wg);                                          // 1 (writes g_X)
    conv2_kernel<<<2048, 256>>>((const float4*)W1, (uint2*)w1,
                                (const float4*)W3, (uint2*)w3,
                                (int)((size_t)E_NUM*D_DIM*H_DIM/4));               // 2
    dispatch_kernel<<<E_NUM, 256>>>();                                             // 3
    up_mma  <<<dim3(CAP/BM, H_DIM/64, E_NUM), 256, DYN_SMEM>>>(H_DIM, 1);          // 4 <- profiled
    convtail_kernel<<<2048, 256>>>((const float4*)W2,  (uint2*)w2,
                                   (const float4*)Ws1, (uint2*)ws1,
                                   (const float4*)Ws3, (uint2*)ws3,
                                   (const float4*)Ws2, (uint2*)ws2);               // 5
    up_mma  <<<dim3(T_TOK/BM, HS_DIM/64, 1), 256, DYN_SMEM>>>(HS_DIM, 0);          // 6
    down_mma<<<dim3(CAP/BM, D_DIM/128, E_NUM), 256, DYN_SMEM>>>(H_DIM, 1, out);    // 7 -> fp16 pairbuf
    down_mma<<<dim3(T_TOK/BM, D_DIM/128, 1), 256, DYN_SMEM>>>(HS_DIM, 0, out);     // 8 dense + fused combine
}

// round 16
// speedup vs baseline: 1.1319x; 1.1319x over previous
#include <cuda_runtime.h>
#include <cuda_fp16.h>
#include <math.h>
#include <stdint.h>

#define T_TOK   4096
#define D_DIM   1024
#define H_DIM   512
#define HS_DIM  1024
#define E_NUM   32
#define TOPK    4
#define P_PAIRS (T_TOK*TOPK)
#define CAP     2048

#define BM 128
#define BK 32
#define STAGE_BYTES 16384
#define N_STAGE 4
#define DYN_SMEM (N_STAGE*STAGE_BYTES)   // 65536

// ---------------- scratch ----------------
__device__ int   g_pair_e[P_PAIRS];
__device__ float g_pair_w[P_PAIRS];
__device__ int   g_pair_pos[P_PAIRS];
__device__ int   g_slot_tok[E_NUM*CAP];
__device__ float g_slot_w[E_NUM*CAP];
__device__ int   g_count[E_NUM];
__device__ __align__(16) __half g_pairbuf[(size_t)E_NUM*CAP*D_DIM];
__device__ __align__(16) __half g_hexp[(size_t)E_NUM*CAP*H_DIM];
__device__ __align__(16) __half g_hsh[(size_t)T_TOK*HS_DIM];
__device__ __align__(16) __half g_X[(size_t)T_TOK*D_DIM];
__device__ __align__(16) __half g_W1[(size_t)E_NUM*D_DIM*H_DIM];
__device__ __align__(16) __half g_W3[(size_t)E_NUM*D_DIM*H_DIM];
__device__ __align__(16) __half g_W2[(size_t)E_NUM*H_DIM*D_DIM];
__device__ __align__(16) __half g_Ws1[(size_t)D_DIM*HS_DIM];
__device__ __align__(16) __half g_Ws3[(size_t)D_DIM*HS_DIM];
__device__ __align__(16) __half g_Ws2[(size_t)HS_DIM*D_DIM];

// ---------------- helpers ----------------
__device__ __forceinline__ uint32_t smem_u32(const void* p) {
    return (uint32_t)__cvta_generic_to_shared(p);
}
__device__ __forceinline__ void cpa16(uint32_t dst, const void* src) {
    asm volatile("cp.async.cg.shared.global [%0], [%1], 16;" :: "r"(dst), "l"(src));
}
__device__ __forceinline__ void cpa16z(uint32_t dst, const void* src, bool valid) {
    int sz = valid ? 16 : 0;
    asm volatile("cp.async.cg.shared.global [%0], [%1], 16, %2;" :: "r"(dst), "l"(src), "r"(sz));
}
__device__ __forceinline__ void cpa_commit() { asm volatile("cp.async.commit_group;"); }
__device__ __forceinline__ void cpa_wait0()  { asm volatile("cp.async.wait_group 0;"); }
__device__ __forceinline__ void cpa_wait1()  { asm volatile("cp.async.wait_group 1;"); }
__device__ __forceinline__ void cpa_wait2()  { asm volatile("cp.async.wait_group 2;"); }
__device__ __forceinline__ void ldsm_x4(uint32_t* r, uint32_t a) {
    asm volatile("ldmatrix.sync.aligned.m8n8.x4.shared.b16 {%0,%1,%2,%3}, [%4];"
        : "=r"(r[0]), "=r"(r[1]), "=r"(r[2]), "=r"(r[3]) : "r"(a));
}
__device__ __forceinline__ void ldsm_x4_t(uint32_t* r, uint32_t a) {
    asm volatile("ldmatrix.sync.aligned.m8n8.x4.trans.shared.b16 {%0,%1,%2,%3}, [%4];"
        : "=r"(r[0]), "=r"(r[1]), "=r"(r[2]), "=r"(r[3]) : "r"(a));
}
__device__ __forceinline__ void mma16816(float* c, const uint32_t* a, const uint32_t* b) {
    asm volatile(
        "mma.sync.aligned.m16n8k16.row.col.f32.f16.f16.f32 "
        "{%0,%1,%2,%3}, {%4,%5,%6,%7}, {%8,%9}, {%0,%1,%2,%3};"
        : "+f"(c[0]), "+f"(c[1]), "+f"(c[2]), "+f"(c[3])
        : "r"(a[0]), "r"(a[1]), "r"(a[2]), "r"(a[3]), "r"(b[0]), "r"(b[1]));
}
__device__ __forceinline__ uint2 conv4h(float4 v) {
    __half2 ab = __floats2half2_rn(v.x, v.y);
    __half2 cd = __floats2half2_rn(v.z, v.w);
    return make_uint2(*(uint32_t*)&ab, *(uint32_t*)&cd);
}
__device__ __forceinline__ uint32_t a_off(int r, int s) {
    return (uint32_t)r*64u + (uint32_t)((s ^ ((r>>1)&3)) << 4);
}
__device__ __forceinline__ uint32_t b_off(int r, int s, int RB) {
    return (uint32_t)r*(uint32_t)RB + (uint32_t)((s ^ (r&7)) << 4);
}

// ---------------- converts ----------------
__global__ __launch_bounds__(256)
void conv2_kernel(const float4* __restrict__ sA, uint2* __restrict__ oA,
                  const float4* __restrict__ sB, uint2* __restrict__ oB, int n4)
{
    for (int i = blockIdx.x*blockDim.x + threadIdx.x; i < n4; i += gridDim.x*blockDim.x) {
        oA[i] = conv4h(sA[i]);
        oB[i] = conv4h(sB[i]);
    }
}
#define N4_W2  ((int)((size_t)E_NUM*H_DIM*D_DIM/4))
#define N4_WS  ((int)((size_t)D_DIM*HS_DIM/4))
__global__ __launch_bounds__(256)
void convtail_kernel(const float4* __restrict__ W2, uint2* __restrict__ oW2,
                     const float4* __restrict__ Ws1, uint2* __restrict__ oWs1,
                     const float4* __restrict__ Ws3, uint2* __restrict__ oWs3,
                     const float4* __restrict__ Ws2, uint2* __restrict__ oWs2)
{
    int total = N4_W2 + 3*N4_WS;
    for (int i = blockIdx.x*blockDim.x + threadIdx.x; i < total; i += gridDim.x*blockDim.x) {
        if (i < N4_W2) {
            oW2[i] = conv4h(W2[i]);
        } else {
            int j = i - N4_W2;
            if (j < N4_WS) oWs1[j] = conv4h(Ws1[j]);
            else if (j < 2*N4_WS) oWs3[j - N4_WS] = conv4h(Ws3[j - N4_WS]);
            else oWs2[j - 2*N4_WS] = conv4h(Ws2[j - 2*N4_WS]);
        }
    }
}

// ---------------- gating: lane = expert, coalesced Wg; also emits fp16 X -------
__global__ __launch_bounds__(256)
void gate_kernel(const float* __restrict__ X, const float* __restrict__ Wg)
{
    int warp = (blockIdx.x*blockDim.x + threadIdx.x) >> 5;
    int lane = threadIdx.x & 31;
    if (warp >= T_TOK) return;
    const float* xr = X + (size_t)warp * D_DIM;
    float xv[32];
    #pragma unroll
    for (int i = 0; i < 32; i++) xv[i] = xr[lane + 32*i];

    __half* xo = g_X + (size_t)warp * D_DIM;
    #pragma unroll
    for (int i = 0; i < 32; i++) xo[lane + 32*i] = __float2half_rn(xv[i]);

    float logit = 0.f;
    #pragma unroll 4
    for (int i0 = 0; i0 < 32; i0++) {
        float xi = xv[i0];
        const float* wrow = Wg + (size_t)(32*i0)*E_NUM + lane;
        #pragma unroll
        for (int l = 0; l < 32; l++) {
            float xk = __shfl_sync(0xffffffffu, xi, l);
            logit += xk * wrow[(size_t)l*E_NUM];
        }
    }

    float m = logit;
    #pragma unroll
    for (int off = 16; off; off >>= 1) m = fmaxf(m, __shfl_xor_sync(0xffffffffu, m, off));
    float p = expf(logit - m);
    float s = p;
    #pragma unroll
    for (int off = 16; off; off >>= 1) s += __shfl_xor_sync(0xffffffffu, s, off);
    float prob = p / s;

    for (int k = 0; k < TOPK; k++) {
        float v = prob; int idx = lane;
        #pragma unroll
        for (int off = 16; off; off >>= 1) {
            float ov = __shfl_xor_sync(0xffffffffu, v, off);
            int   oi = __shfl_xor_sync(0xffffffffu, idx, off);
            if (ov > v || (ov == v && oi < idx)) { v = ov; idx = oi; }
        }
        if (lane == 0) {
            g_pair_e[warp*TOPK + k] = idx;
            g_pair_w[warp*TOPK + k] = v;
        }
        if (lane == idx) prob = -1.f;
    }
}

// ---------------- dispatch ----------------
__global__ __launch_bounds__(256)
void dispatch_kernel()
{
    int e = blockIdx.x;
    int tid = threadIdx.x;
    int lane = tid & 31, wid = tid >> 5;
    __shared__ int wtot[8];
    __shared__ int s_run;
    if (tid == 0) s_run = 0;
    __syncthreads();

    for (int base = 0; base < P_PAIRS; base += 256) {
        int p = base + tid;
        int flag = (g_pair_e[p] == e) ? 1 : 0;
        unsigned b = __ballot_sync(0xffffffffu, flag);
        int woff = __popc(b & ((1u << lane) - 1u));
        if (lane == 0) wtot[wid] = __popc(b);
        __syncthreads();
        int excl = 0, tot = 0;
        #pragma unroll
        for (int w = 0; w < 8; w++) { if (w < wid) excl += wtot[w]; tot += wtot[w]; }
        int pos = s_run + excl + woff;
        if (flag) {
            if (pos < CAP) {
                g_slot_tok[e*CAP + pos] = p >> 2;
                g_slot_w  [e*CAP + pos] = g_pair_w[p];
                g_pair_pos[p] = e*CAP + pos;
            } else {
                g_pair_pos[p] = -1;
            }
        }
        __syncthreads();
        if (tid == 0) s_run += tot;
        __syncthreads();
    }
    if (tid == 0) g_count[e] = min(s_run, CAP);
}

// =====================================================================
// up (templated, R14 config): block 128x64, 256 thr, occ 2, 4-stage BK=32
// =====================================================================
template<int NN, bool EXPERT>
__global__ __launch_bounds__(256, 2)
void up_mma()
{
    extern __shared__ char sm[];
    uint32_t sbase = smem_u32(sm);
    constexpr int KK = D_DIM;
    constexpr int NT = KK / BK;

    int e = blockIdx.z;
    int M_eff; const int* rows = nullptr;
    const __half *B1_g, *B3_g;
    __half *Hh;
    if (EXPERT) {
        M_eff = g_count[e];
        rows  = g_slot_tok + e*CAP;
        size_t wo = (size_t)e*D_DIM*H_DIM;
        B1_g = g_W1 + wo; B3_g = g_W3 + wo;
        Hh = g_hexp + (size_t)e*CAP*NN;
    } else {
        M_eff = T_TOK;
        B1_g = g_Ws1; B3_g = g_Ws3;
        Hh = g_hsh;
    }
    int mbase = blockIdx.x * BM;
    if (mbase >= M_eff) return;
    int nbase = blockIdx.y * 64;

    int tid = threadIdx.x, lane = tid & 31, wid = tid >> 5;
    int wm = wid >> 2, wn = wid & 3;

    int ar0 = tid >> 2, as = tid & 3;
    bool avA[2]; const __half* XP[2];
    #pragma unroll
    for (int h = 0; h < 2; h++) {
        int slot = mbase + ar0 + h*64;
        avA[h] = slot < M_eff;
        int tok = avA[h] ? (EXPERT ? rows[slot] : slot) : 0;
        XP[h] = g_X + (size_t)tok*KK + as*8;
    }
    int brow = tid >> 3, bs = tid & 7;

    auto load_stage = [&](int s, int kt) {
        uint32_t st = sbase + (uint32_t)s*STAGE_BYTES;
        #pragma unroll
        for (int h = 0; h < 2; h++)
            cpa16z(st + a_off(ar0 + h*64, as), XP[h] + kt, avA[h]);
        uint32_t d = b_off(brow, bs, 128);
        size_t src = (size_t)(kt + brow)*NN + nbase + bs*8;
        cpa16(st + 8192  + d, B1_g + src);
        cpa16(st + 12288 + d, B3_g + src);
        cpa_commit();
    };

    float c1[4][2][4] = {}, c3[4][2][4] = {};

    load_stage(0, 0);
    load_stage(1, BK);
    load_stage(2, 2*BK);
    #pragma unroll 4
    for (int t = 0; t < NT; t++) {
        int s = t & 3;
        if (t < NT - 2) cpa_wait2(); else if (t == NT - 2) cpa_wait1(); else cpa_wait0();
        __syncthreads();
        if (t + 3 < NT) load_stage((t + 3) & 3, (t + 3) * BK);

        uint32_t st = sbase + (uint32_t)s*STAGE_BYTES;
        #pragma unroll
        for (int ks = 0; ks < 2; ks++) {
            int k0 = ks * 16;
            int rr = k0 + (lane & 7) + ((lane >> 3) & 1) * 8;
            int cc = wn*16 + (lane >> 4) * 8;
            uint32_t boff = b_off(rr, cc >> 3, 128);
            uint32_t b1[4], b3[4];
            ldsm_x4_t(b1, st + 8192  + boff);
            ldsm_x4_t(b3, st + 12288 + boff);
            #pragma unroll
            for (int mt = 0; mt < 4; mt++) {
                int r = wm*64 + mt*16 + (lane & 15);
                int sA = (k0 >> 3) + (lane >> 4);
                uint32_t ah[4];
                ldsm_x4(ah, st + a_off(r, sA));
                #pragma unroll
                for (int nt = 0; nt < 2; nt++) {
                    mma16816(c1[mt][nt], ah, &b1[nt*2]);
                    mma16816(c3[mt][nt], ah, &b3[nt*2]);
                }
            }
        }
    }

    int r0 = lane >> 2, cb = (lane & 3) * 2;
    #pragma unroll
    for (int mt = 0; mt < 4; mt++)
        #pragma unroll
        for (int nt = 0; nt < 2; nt++) {
            int n = nbase + wn*16 + nt*8 + cb;
            #pragma unroll
            for (int p = 0; p < 2; p++) {
                int m = mbase + wm*64 + mt*16 + r0 + p*8;
                if (m < M_eff) {
                    float g0 = c1[mt][nt][2*p+0], g1 = c1[mt][nt][2*p+1];
                    float v0 = g0 / (1.f + expf(-g0)) * c3[mt][nt][2*p+0];
                    float v1 = g1 / (1.f + expf(-g1)) * c3[mt][nt][2*p+1];
                    __half2 hv = __floats2half2_rn(v0, v1);
                    *(uint32_t*)&Hh[(size_t)m*NN + n] = *(uint32_t*)&hv;
                }
            }
        }
}

// =====================================================================
// down (templated, R14 config): block 128x128, 256 thr, occ 2, 4-stage BK=32
// EXPERT: weighted rows -> fp16 pairbuf; else dense + fused combine
// =====================================================================
template<int KK, bool EXPERT>
__global__ __launch_bounds__(256, 2)
void down_mma(float* __restrict__ out)
{
    extern __shared__ char sm[];
    uint32_t sbase = smem_u32(sm);
    constexpr int NT = KK / BK;

    int e = blockIdx.z;
    int M_eff; const float* wv = nullptr;
    const __half *A_g, *B_g;
    if (EXPERT) {
        M_eff = g_count[e];
        wv    = g_slot_w  + e*CAP;
        B_g   = g_W2 + (size_t)e*H_DIM*D_DIM;
        A_g   = g_hexp + (size_t)e*CAP*KK;
    } else {
        M_eff = T_TOK;
        B_g   = g_Ws2;
        A_g   = g_hsh;
    }
    int mbase = blockIdx.x * BM;
    if (mbase >= M_eff) return;
    int nbase = blockIdx.y * 128;

    int tid = threadIdx.x, lane = tid & 31, wid = tid >> 5;
    int wm = wid >> 2, wn = wid & 3;

    int ar0 = tid >> 2, as = tid & 3;
    bool avA[2]; const __half* AP[2];
    #pragma unroll
    for (int h = 0; h < 2; h++) {
        int slot = mbase + ar0 + h*64;
        avA[h] = slot < M_eff;
        int rr = avA[h] ? slot : mbase;
        AP[h] = A_g + (size_t)rr*KK + as*8;
    }
    int br0 = tid >> 4, bs0 = tid & 15;

    auto load_stage = [&](int s, int kt) {
        uint32_t st = sbase + (uint32_t)s*STAGE_BYTES;
        #pragma unroll
        for (int h = 0; h < 2; h++)
            cpa16z(st + a_off(ar0 + h*64, as), AP[h] + kt, avA[h]);
        #pragma unroll
        for (int h = 0; h < 2; h++) {
            int r = br0 + h*16;
            cpa16(st + 8192 + b_off(r, bs0, 256),
                  B_g + (size_t)(kt + r)*D_DIM + nbase + bs0*8);
        }
        cpa_commit();
    };

    float c[4][4][4] = {};

    load_stage(0, 0);
    load_stage(1, BK);
    load_stage(2, 2*BK);
    #pragma unroll 4
    for (int t = 0; t < NT; t++) {
        int s = t & 3;
        if (t < NT - 2) cpa_wait2(); else if (t == NT - 2) cpa_wait1(); else cpa_wait0();
        __syncthreads();
        if (t + 3 < NT) load_stage((t + 3) & 3, (t + 3) * BK);

        uint32_t st = sbase + (uint32_t)s*STAGE_BYTES;
        #pragma unroll
        for (int ks = 0; ks < 2; ks++) {
            int k0 = ks * 16;
            int rr = k0 + (lane & 7) + ((lane >> 3) & 1) * 8;
            uint32_t bf[2][4];
            #pragma unroll
            for (int h = 0; h < 2; h++) {
                int cc = wn*32 + h*16 + (lane >> 4) * 8;
                ldsm_x4_t(bf[h], st + 8192 + b_off(rr, cc >> 3, 256));
            }
            #pragma unroll
            for (int mt = 0; mt < 4; mt++) {
                int r = wm*64 + mt*16 + (lane & 15);
                int sA = (k0 >> 3) + (lane >> 4);
                uint32_t ah[4];
                ldsm_x4(ah, st + a_off(r, sA));
                #pragma unroll
                for (int nt = 0; nt < 4; nt++)
                    mma16816(c[mt][nt], ah, &bf[nt>>1][(nt&1)*2]);
            }
        }
    }

    int r0 = lane >> 2, cb = (lane & 3) * 2;
    #pragma unroll
    for (int mt = 0; mt < 4; mt++) {
        #pragma unroll
        for (int p = 0; p < 2; p++) {
            int m = mbase + wm*64 + mt*16 + r0 + p*8;
            if (m >= M_eff) continue;
            if (EXPERT) {
                float w = wv[m];
                __half* orow = g_pairbuf + (size_t)(e*CAP + m)*D_DIM;
                #pragma unroll
                for (int nt = 0; nt < 4; nt++) {
                    int n = nbase + wn*32 + nt*8 + cb;
                    __half2 hv = __floats2half2_rn(c[mt][nt][2*p+0] * w,
                                                   c[mt][nt][2*p+1] * w);
                    *(uint32_t*)&orow[n] = *(uint32_t*)&hv;
                }
            } else {
                int4 pos4 = *(const int4*)&g_pair_pos[m*TOPK];
                int posv[4] = {pos4.x, pos4.y, pos4.z, pos4.w};
                float* orow = out + (size_t)m*D_DIM;
                #pragma unroll
                for (int nt = 0; nt < 4; nt++) {
                    int n = nbase + wn*32 + nt*8 + cb;
                    float v0 = c[mt][nt][2*p+0], v1 = c[mt][nt][2*p+1];
                    #pragma unroll
                    for (int k = 0; k < TOPK; k++) {
                        if (posv[k] >= 0) {
                            uint32_t hv = *(const uint32_t*)
                                &g_pairbuf[(size_t)posv[k]*D_DIM + n];
                            float2 f = __half22float2(*(__half2*)&hv);
                            v0 += f.x; v1 += f.y;
                        }
                    }
                    *(float2*)&orow[n] = make_float2(v0, v1);
                }
            }
        }
    }
}

// ---------------- host launcher ----------------
extern "C" void kernel_launch(void* const* d_in, const int* in_sizes, int n_in,
                              void* d_out, int out_size)
{
    const float* x   = (const float*)d_in[0];
    const float* Wg  = (const float*)d_in[1];
    const float* W1  = (const float*)d_in[2];
    const float* W2  = (const float*)d_in[3];
    const float* W3  = (const float*)d_in[4];
    const float* Ws1 = (const float*)d_in[5];
    const float* Ws2 = (const float*)d_in[6];
    const float* Ws3 = (const float*)d_in[7];
    float* out = (float*)d_out;

    cudaFuncSetAttribute(up_mma<H_DIM,  true >, cudaFuncAttributeMaxDynamicSharedMemorySize, DYN_SMEM);
    cudaFuncSetAttribute(up_mma<HS_DIM, false>, cudaFuncAttributeMaxDynamicSharedMemorySize, DYN_SMEM);
    cudaFuncSetAttribute(down_mma<H_DIM,  true >, cudaFuncAttributeMaxDynamicSharedMemorySize, DYN_SMEM);
    cudaFuncSetAttribute(down_mma<HS_DIM, false>, cudaFuncAttributeMaxDynamicSharedMemorySize, DYN_SMEM);

    void *w1, *w3, *w2, *ws1, *ws3, *ws2;
    cudaGetSymbolAddress(&w1, g_W1);  cudaGetSymbolAddress(&w3, g_W3);
    cudaGetSymbolAddress(&w2, g_W2);
    cudaGetSymbolAddress(&ws1, g_Ws1); cudaGetSymbolAddress(&ws3, g_Ws3);
    cudaGetSymbolAddress(&ws2, g_Ws2);

    gate_kernel<<<T_TOK/8, 256>>>(x, Wg);                                          // 1 (writes g_X)
    conv2_kernel<<<2048, 256>>>((const float4*)W1, (uint2*)w1,
                                (const float4*)W3, (uint2*)w3,
                                (int)((size_t)E_NUM*D_DIM*H_DIM/4));               // 2
    dispatch_kernel<<<E_NUM, 256>>>();                                             // 3
    up_mma<H_DIM, true><<<dim3(CAP/BM, H_DIM/64, E_NUM), 256, DYN_SMEM>>>();       // 4 <- profiled
    convtail_kernel<<<2048, 256>>>((const float4*)W2,  (uint2*)w2,
                                   (const float4*)Ws1, (uint2*)ws1,
                                   (const float4*)Ws3, (uint2*)ws3,
                                   (const float4*)Ws2, (uint2*)ws2);               // 5
    up_mma<HS_DIM, false><<<dim3(T_TOK/BM, HS_DIM/64, 1), 256, DYN_SMEM>>>();      // 6
    down_mma<H_DIM, true><<<dim3(CAP/BM, D_DIM/128, E_NUM), 256, DYN_SMEM>>>(out); // 7 -> fp16 pairbuf
    down_mma<HS_DIM, false><<<dim3(T_TOK/BM, D_DIM/128, 1), 256, DYN_SMEM>>>(out); // 8 dense + fused combine
}